// round 6
// baseline (speedup 1.0000x reference)
#include <cuda_runtime.h>
#include <math.h>

#define BB 16
#define DD 512
#define HH 16
#define HD 32
#define LL 24
#define DFF 2048
#define NQKV 1536
#define TMAX 1024
#define NT 512

// ---------------- device scratch ----------------
__device__ float g_h[BB * DD];          // layer input h (post LN2 of prev)
__device__ float g_h1[BB * DD];         // post-LN1 hidden
__device__ float g_attn[BB * DD];       // attention output
__device__ float g_po[4 * BB * DD];     // outproj K-partials
__device__ float g_act[BB * DFF];       // relu(mlp1) final
__device__ float g_p2[4 * BB * DD];     // mlp2 K-partials
__device__ unsigned g_bar_count;
__device__ volatile unsigned g_bar_gen;

// ---------------- grid barrier ----------------
__device__ __forceinline__ void gsync() {
    __syncthreads();
    if (threadIdx.x == 0) {
        unsigned gen = g_bar_gen;
        __threadfence();
        if (atomicAdd(&g_bar_count, 1u) == gridDim.x - 1) {
            g_bar_count = 0;
            __threadfence();
            g_bar_gen = gen + 1;
        } else {
            while (g_bar_gen == gen) __nanosleep(64);
            __threadfence();
        }
    }
    __syncthreads();
}

// =============== S_A: fused LN2(prev) + qkv GEMV + attention ==============
// one block per (b, h), 512 threads.
__device__ void attn_fused(int l, int b, int h,
                           const float* __restrict__ x,
                           const float* __restrict__ Kc,
                           const float* __restrict__ Vc,
                           const float* __restrict__ Wq,
                           const float* __restrict__ bq,
                           const float* __restrict__ b2p,   // prev-layer mlp2 bias
                           const float* __restrict__ g2p,   // prev-layer ln2 gamma
                           const float* __restrict__ be2p,  // prev-layer ln2 beta
                           const int* __restrict__ kvlen, float* sm) {
    float* hb   = sm;           // [512]
    float* sc   = sm + 512;     // [1028]
    float* qred = sm + 1540;    // [4*96]
    float* qs   = sm + 1924;    // [32]
    float* kns  = sm + 1956;    // [32]
    float* vns  = sm + 1988;    // [32]
    float* redv = sm + 2020;    // [16*32]
    float* rr   = sm + 2532;    // [16]
    float* fin  = sm + 2548;    // [2]

    const int tid = threadIdx.x, wid = tid >> 5, lane = tid & 31;
    const int T = kvlen[b];
    const float* Kb = Kc + ((size_t)b * HH + h) * TMAX * HD;
    const float* Vb = Vc + ((size_t)b * HH + h) * TMAX * HD;

    // prefetch this block's K/V rows while we compute LN + qkv
    for (int i = tid; i < T; i += NT) {
        asm volatile("prefetch.global.L2 [%0];" :: "l"(Kb + (size_t)i * HD));
        asm volatile("prefetch.global.L2 [%0];" :: "l"(Vb + (size_t)i * HD));
    }

    // ---- 1) hb = h[b]: x for l==0, else LN2(h1 + b2 + sum of 4 partials)
    {
        const int d = tid;
        if (l == 0) {
            hb[d] = x[(size_t)b * DD + d];
        } else {
            float v = g_h1[(size_t)b * DD + d] + b2p[d];
#pragma unroll
            for (int s = 0; s < 4; s++) v += g_p2[(size_t)(s * BB + b) * DD + d];
            float s1 = v, s2 = v * v;
#pragma unroll
            for (int o = 16; o; o >>= 1) {
                s1 += __shfl_xor_sync(0xffffffffu, s1, o);
                s2 += __shfl_xor_sync(0xffffffffu, s2, o);
            }
            if (lane == 0) { rr[wid] = s1; redv[wid] = s2; }
            __syncthreads();
            if (tid == 0) {
                float a = 0.f, q = 0.f;
#pragma unroll
                for (int w = 0; w < 16; w++) { a += rr[w]; q += redv[w]; }
                float mean = a / DD;
                fin[0] = mean;
                fin[1] = rsqrtf(q / DD - mean * mean + 1e-5f);
            }
            __syncthreads();
            hb[d] = (v - fin[0]) * fin[1] * g2p[d] + be2p[d];
        }
        if (h == 0) g_h[(size_t)b * DD + d] = hb[d];
    }
    __syncthreads();

    // ---- 2) qkv GEMV for this head's 96 columns (4 K-slices of 128)
    {
        const int ks = tid >> 7, c = tid & 127;
        if (c < 96) {
            const int gcol = (c >> 5) * DD + h * HD + (c & 31);
            const float* wp = Wq + (size_t)(ks * 128) * NQKV + gcol;
            const float* xp = hb + ks * 128;
            float acc = 0.f;
#pragma unroll 8
            for (int d = 0; d < 128; d++) acc += xp[d] * wp[(size_t)d * NQKV];
            qred[ks * 96 + c] = acc;
        }
        __syncthreads();
        if (tid < 96) {
            const int gcol = (tid >> 5) * DD + h * HD + (tid & 31);
            float v = bq[gcol] + qred[tid] + qred[96 + tid] +
                      qred[192 + tid] + qred[288 + tid];
            const int j = tid & 31;
            if (tid < 32) qs[j] = v;
            else if (tid < 64) kns[j] = v;
            else vns[j] = v;
        }
        __syncthreads();
    }

    // ---- 3) scores: thread per timestep
    const float scale = 0.17677669529663687f;
    for (int t = tid; t <= T; t += NT) {
        const float* kp = (t < T) ? (Kb + (size_t)t * HD) : kns;
        float s = 0.f;
#pragma unroll
        for (int i = 0; i < 8; i++) {
            float4 k4 = *(const float4*)(kp + i * 4);
            float4 q4 = *(const float4*)(qs + i * 4);
            s += k4.x * q4.x + k4.y * q4.y + k4.z * q4.z + k4.w * q4.w;
        }
        sc[t] = s * scale;
    }
    __syncthreads();

    // ---- 4) softmax (full, no chunking)
    float m = -1e30f;
    for (int t = tid; t <= T; t += NT) m = fmaxf(m, sc[t]);
#pragma unroll
    for (int o = 16; o; o >>= 1) m = fmaxf(m, __shfl_xor_sync(0xffffffffu, m, o));
    if (lane == 0) rr[wid] = m;
    __syncthreads();
    if (tid == 0) {
        float mm = rr[0];
#pragma unroll
        for (int w = 1; w < 16; w++) mm = fmaxf(mm, rr[w]);
        fin[0] = mm;
    }
    __syncthreads();
    m = fin[0];

    float s = 0.f;
    for (int t = tid; t <= T; t += NT) {
        float e = __expf(sc[t] - m);
        sc[t] = e;
        s += e;
    }
#pragma unroll
    for (int o = 16; o; o >>= 1) s += __shfl_xor_sync(0xffffffffu, s, o);
    if (lane == 0) rr[wid] = s;
    __syncthreads();
    if (tid == 0) {
        float ss = rr[0];
#pragma unroll
        for (int w = 1; w < 16; w++) ss += rr[w];
        fin[1] = 1.0f / ss;
    }
    __syncthreads();
    const float invS = fin[1];

    // ---- 5) V pass: warp covers 4 timesteps/iter
    const int tq = lane >> 3, dq = lane & 7;
    float4 acc = make_float4(0.f, 0.f, 0.f, 0.f);
#pragma unroll 2
    for (int t = wid * 4 + tq; t <= T; t += 64) {
        float wgt = sc[t];
        const float* vp = (t < T) ? (Vb + (size_t)t * HD) : vns;
        float4 v4 = *(const float4*)(vp + dq * 4);
        acc.x += wgt * v4.x; acc.y += wgt * v4.y;
        acc.z += wgt * v4.z; acc.w += wgt * v4.w;
    }
#pragma unroll
    for (int o = 8; o <= 16; o <<= 1) {
        acc.x += __shfl_xor_sync(0xffffffffu, acc.x, o);
        acc.y += __shfl_xor_sync(0xffffffffu, acc.y, o);
        acc.z += __shfl_xor_sync(0xffffffffu, acc.z, o);
        acc.w += __shfl_xor_sync(0xffffffffu, acc.w, o);
    }
    if (tq == 0) *(float4*)(redv + wid * 32 + dq * 4) = acc;
    __syncthreads();
    if (tid < HD) {
        float o = 0.f;
#pragma unroll
        for (int w = 0; w < 16; w++) o += redv[w * 32 + tid];
        g_attn[(size_t)b * DD + h * HD + tid] = o * invS;
    }
}

// =============== GEMV machinery (32 cols x 16 batches) =====================
template <int DS>
__device__ __forceinline__ void preload_plain(const float* __restrict__ src,
                                              int ld, int d0, float* xs) {
    const int tid = threadIdx.x;
#pragma unroll
    for (int i = tid; i < DS * BB; i += NT) {
        int bb = i / DS, d = i % DS;
        xs[d * 20 + bb] = src[(size_t)bb * ld + d0 + d];
    }
    __syncthreads();
}

// LN1 fused preload: warp w = batch w; merge 4 outproj partials + resid + bias.
__device__ __forceinline__ void preload_ln1(const float* __restrict__ bo,
                                            const float* __restrict__ gam,
                                            const float* __restrict__ bet,
                                            float* xs, int wstore) {
    const int lane = threadIdx.x & 31, w = threadIdx.x >> 5;
    float vals[16];
    float s1 = 0.f, s2 = 0.f;
#pragma unroll
    for (int jj = 0; jj < 16; jj++) {
        int d = lane + jj * 32;
        float v = g_h[(size_t)w * DD + d] + bo[d];
#pragma unroll
        for (int s = 0; s < 4; s++) v += g_po[(size_t)(s * BB + w) * DD + d];
        vals[jj] = v;
        s1 += v;
        s2 += v * v;
    }
#pragma unroll
    for (int o = 16; o; o >>= 1) {
        s1 += __shfl_xor_sync(0xffffffffu, s1, o);
        s2 += __shfl_xor_sync(0xffffffffu, s2, o);
    }
    const float mean = s1 * (1.0f / DD);
    const float rstd = rsqrtf(s2 * (1.0f / DD) - mean * mean + 1e-5f);
#pragma unroll
    for (int jj = 0; jj < 16; jj++) {
        int d = lane + jj * 32;
        float o = (vals[jj] - mean) * rstd * gam[d] + bet[d];
        xs[d * 20 + w] = o;
        if (wstore) g_h1[(size_t)w * DD + d] = o;
    }
    __syncthreads();
}

template <int DS>
__device__ __forceinline__ void gemv_core(const float* __restrict__ W, int N,
                                          int d0, int c0,
                                          float* __restrict__ out, int ldo,
                                          const float* __restrict__ bias,
                                          int relu, float* xs, float* red) {
    const int tid = threadIdx.x, lane = tid & 31, w = tid >> 5;
    constexpr int DW = DS / 16;
    const float* Wp = W + (size_t)(d0 + w * DW) * N + c0 + lane;
    const float* xp = xs + (size_t)(w * DW) * 20;
    float acc[16];
#pragma unroll
    for (int b = 0; b < 16; b++) acc[b] = 0.f;
#pragma unroll 8
    for (int d = 0; d < DW; d++) {
        float wv = Wp[(size_t)d * N];
        float4 x0 = *(const float4*)(xp + d * 20);
        float4 x1 = *(const float4*)(xp + d * 20 + 4);
        float4 x2 = *(const float4*)(xp + d * 20 + 8);
        float4 x3 = *(const float4*)(xp + d * 20 + 12);
        acc[0]  += x0.x * wv; acc[1]  += x0.y * wv;
        acc[2]  += x0.z * wv; acc[3]  += x0.w * wv;
        acc[4]  += x1.x * wv; acc[5]  += x1.y * wv;
        acc[6]  += x1.z * wv; acc[7]  += x1.w * wv;
        acc[8]  += x2.x * wv; acc[9]  += x2.y * wv;
        acc[10] += x2.z * wv; acc[11] += x2.w * wv;
        acc[12] += x3.x * wv; acc[13] += x3.y * wv;
        acc[14] += x3.z * wv; acc[15] += x3.w * wv;
    }
    float* rp = red + (size_t)tid * 17;
#pragma unroll
    for (int b = 0; b < 16; b++) rp[b] = acc[b];
    __syncthreads();
    const int cc = tid & 31, bb = tid >> 5;
    float v = 0.f;
#pragma unroll
    for (int w2 = 0; w2 < 16; w2++) v += red[(size_t)(w2 * 32 + cc) * 17 + bb];
    if (bias) v += bias[c0 + cc];
    if (relu) v = fmaxf(v, 0.f);
    out[(size_t)bb * ldo + c0 + cc] = v;
    __syncthreads();
}

// ---------------- final LN2 -> d_out: one batch per vblock ----------------
__device__ void ln_final(const float* __restrict__ b2p,
                         const float* __restrict__ gam,
                         const float* __restrict__ bet,
                         float* __restrict__ dout, int b, float* sm) {
    const int tid = threadIdx.x, lane = tid & 31, wid = tid >> 5;
    float v = g_h1[(size_t)b * DD + tid] + b2p[tid];
#pragma unroll
    for (int s = 0; s < 4; s++) v += g_p2[(size_t)(s * BB + b) * DD + tid];
    float s1 = v, s2 = v * v;
#pragma unroll
    for (int o = 16; o; o >>= 1) {
        s1 += __shfl_xor_sync(0xffffffffu, s1, o);
        s2 += __shfl_xor_sync(0xffffffffu, s2, o);
    }
    float* rs = sm; float* rq = sm + 16; float* mv = sm + 32;
    if (lane == 0) { rs[wid] = s1; rq[wid] = s2; }
    __syncthreads();
    if (tid == 0) {
        float a = 0.f, q = 0.f;
#pragma unroll
        for (int w = 0; w < 16; w++) { a += rs[w]; q += rq[w]; }
        float mean = a / DD;
        mv[0] = mean;
        mv[1] = rsqrtf(q / DD - mean * mean + 1e-5f);
    }
    __syncthreads();
    dout[(size_t)b * DD + tid] = (v - mv[0]) * mv[1] * gam[tid] + bet[tid];
    __syncthreads();
}

// ---------------- persistent kernel ----------------
__global__ void __launch_bounds__(NT, 2)
decoder_kernel(const float* __restrict__ x,
               const float* __restrict__ kc, const float* __restrict__ vc,
               const float* __restrict__ ln1g, const float* __restrict__ ln1b,
               const float* __restrict__ qkvw, const float* __restrict__ qkvb,
               const float* __restrict__ outw, const float* __restrict__ outb,
               const float* __restrict__ ln2g, const float* __restrict__ ln2b,
               const float* __restrict__ w1, const float* __restrict__ b1,
               const float* __restrict__ w2, const float* __restrict__ b2,
               const int* __restrict__ kvlen, float* __restrict__ dout) {
    extern __shared__ float sm[];
    float* xs  = sm;             // [512][20] max
    float* red = sm + 512 * 20;  // [512][17]

    for (int l = 0; l < LL; l++) {
        const float* Wq = qkvw + (size_t)l * DD * NQKV;
        const float* bq = qkvb + (size_t)l * NQKV;
        const float* Wo = outw + (size_t)l * DD * DD;
        const float* bo = outb + (size_t)l * DD;
        const float* W1 = w1 + (size_t)l * DD * DFF;
        const float* B1 = b1 + (size_t)l * DFF;
        const float* W2 = w2 + (size_t)l * DFF * DD;
        const float* Kc = kc + (size_t)l * BB * HH * TMAX * HD;
        const float* Vc = vc + (size_t)l * BB * HH * TMAX * HD;
        const float* b2p  = b2 + (size_t)(l ? l - 1 : 0) * DD;
        const float* g2p  = ln2g + (size_t)(l ? l - 1 : 0) * DD;
        const float* be2p = ln2b + (size_t)(l ? l - 1 : 0) * DD;

        // S_A: fused LN2(prev) + qkv + attention. 256 vblocks.
        for (int vb = blockIdx.x; vb < 256; vb += gridDim.x)
            attn_fused(l, vb >> 4, vb & 15, x, Kc, Vc, Wq, bq,
                       b2p, g2p, be2p, kvlen, sm);
        gsync();

        // S_B: outproj split-K4 (DS=128). 64 vblocks.
        for (int vb = blockIdx.x; vb < 64; vb += gridDim.x) {
            int ks = vb & 3, c0 = (vb >> 2) * 32;
            preload_plain<128>(g_attn, DD, ks * 128, xs);
            gemv_core<128>(Wo, DD, ks * 128, c0,
                           g_po + (size_t)ks * BB * DD, DD, nullptr, 0, xs, red);
        }
        gsync();

        // S_C: mlp1 full-K with fused LN1 preload; bias+relu epilogue. 64 vblocks.
        for (int vb = blockIdx.x; vb < 64; vb += gridDim.x) {
            preload_ln1(bo, ln1g + (size_t)l * DD, ln1b + (size_t)l * DD,
                        xs, vb == 0);
            gemv_core<512>(W1, DFF, 0, vb * 32, g_act, DFF, B1, 1, xs, red);
        }
        gsync();

        // S_D: mlp2 split-K4 (DS=512). 64 vblocks.
        for (int vb = blockIdx.x; vb < 64; vb += gridDim.x) {
            int ks = vb & 3, c0 = (vb >> 2) * 32;
            preload_plain<512>(g_act, DFF, ks * 512, xs);
            gemv_core<512>(W2, DD, ks * 512, c0,
                           g_p2 + (size_t)ks * BB * DD, DD, nullptr, 0, xs, red);
        }
        gsync();
    }

    // final LN2 -> d_out. 16 vblocks.
    for (int vb = blockIdx.x; vb < 16; vb += gridDim.x)
        ln_final(b2 + (size_t)(LL - 1) * DD,
                 ln2g + (size_t)(LL - 1) * DD, ln2b + (size_t)(LL - 1) * DD,
                 dout, vb, sm);
}

// ---------------- launcher ----------------
extern "C" void kernel_launch(void* const* d_in, const int* in_sizes, int n_in,
                              void* d_out, int out_size) {
    (void)in_sizes; (void)n_in; (void)out_size;
    const float* x    = (const float*)d_in[0];
    const float* kc   = (const float*)d_in[1];
    const float* vc   = (const float*)d_in[2];
    const float* ln1g = (const float*)d_in[3];
    const float* ln1b = (const float*)d_in[4];
    const float* qkvw = (const float*)d_in[5];
    const float* qkvb = (const float*)d_in[6];
    const float* outw = (const float*)d_in[7];
    const float* outb = (const float*)d_in[8];
    const float* ln2g = (const float*)d_in[9];
    const float* ln2b = (const float*)d_in[10];
    const float* w1   = (const float*)d_in[11];
    const float* b1   = (const float*)d_in[12];
    const float* w2   = (const float*)d_in[13];
    const float* b2   = (const float*)d_in[14];
    const int* kvlen  = (const int*)d_in[16];

    static int grid = 0;
    const int SMEM = (512 * 20 + 512 * 17) * 4;  // 75776 bytes
    if (!grid) {
        cudaFuncSetAttribute(decoder_kernel,
                             cudaFuncAttributeMaxDynamicSharedMemorySize, SMEM);
        int dev = 0;
        cudaGetDevice(&dev);
        cudaDeviceProp prop;
        cudaGetDeviceProperties(&prop, dev);
        int occ = 0;
        cudaOccupancyMaxActiveBlocksPerMultiprocessor(&occ, decoder_kernel,
                                                      NT, SMEM);
        if (occ < 1) occ = 1;
        if (occ > 2) occ = 2;
        grid = prop.multiProcessorCount * occ;
    }

    decoder_kernel<<<grid, NT, SMEM>>>(
        x, kc, vc, ln1g, ln1b, qkvw, qkvb, outw, outb, ln2g, ln2b,
        w1, b1, w2, b2, kvlen, (float*)d_out);
}

// round 7
// speedup vs baseline: 1.2132x; 1.2132x over previous
#include <cuda_runtime.h>
#include <math.h>

#define BB 16
#define DD 512
#define HH 16
#define HD 32
#define LL 24
#define DFF 2048
#define NQKV 1536
#define TMAX 1024
#define NT 256
#define NCH 2  // attention T-chunks

// ---------------- device scratch ----------------
__device__ float g_h[BB * DD];            // layer input (post LN2 of prev layer)
__device__ float g_h1[BB * DD];           // post-LN1 hidden
__device__ float g_pqkv[4 * BB * NQKV];   // qkv K-partials
__device__ float g_po[16 * BB * DD];      // outproj K-partials
__device__ float g_pm1[4 * BB * DFF];     // mlp1 K-partials
__device__ float g_p2[16 * BB * DD];      // mlp2 K-partials
__device__ float g_am[BB * HH * NCH];     // per-chunk softmax max
__device__ float g_as[BB * HH * NCH];     // per-chunk exp-sum
__device__ float g_ao[NCH * BB * HH * HD];// per-chunk unnormalized V-acc
__device__ unsigned g_bar_count;
__device__ volatile unsigned g_bar_gen;

// ---------------- grid barrier ----------------
__device__ __forceinline__ void gsync() {
    __syncthreads();
    if (threadIdx.x == 0) {
        unsigned gen = g_bar_gen;
        __threadfence();
        if (atomicAdd(&g_bar_count, 1u) == gridDim.x - 1) {
            g_bar_count = 0;
            __threadfence();
            g_bar_gen = gen + 1;
        } else {
            while (g_bar_gen == gen) __nanosleep(64);
            __threadfence();
        }
    }
    __syncthreads();
}

// ---------------- plain preload: src[b][d0+d] -> xs[d][bb] ----------------
template <int DS>
__device__ __forceinline__ void preload_plain(const float* __restrict__ src, int ld,
                                              int d0, int b0, float* xs) {
    const int tid = threadIdx.x;
#pragma unroll
    for (int i = tid; i < DS * 8; i += NT) {
        int bb = i / DS, d = i % DS;
        xs[d * 12 + bb] = src[(size_t)(b0 + bb) * ld + d0 + d];
    }
    __syncthreads();
}

// ---------------- mlp2 preload: relu(b1 + sum of 4 mlp1 partials) --------
__device__ __forceinline__ void preload_relu(const float* __restrict__ b1,
                                             int d0, int b0, float* xs) {
    const int tid = threadIdx.x;
#pragma unroll
    for (int i = tid; i < 128 * 8; i += NT) {
        int bb = i >> 7, d = i & 127;
        int gd = d0 + d;
        float v = b1[gd];
#pragma unroll
        for (int s = 0; s < 4; s++)
            v += g_pm1[(size_t)(s * BB + b0 + bb) * DFF + gd];
        xs[d * 12 + bb] = fmaxf(v, 0.f);
    }
    __syncthreads();
}

// ---------------- outproj preload: merge NCH attention chunks ------------
__device__ __forceinline__ void preload_attn(int h, int b0, float* xs) {
    const int tid = threadIdx.x;
    const int bb = tid >> 5, j = tid & 31;
    const int b = b0 + bb;
    const int base = (b * HH + h) * NCH;
    float m0 = g_am[base + 0], m1 = g_am[base + 1];
    float m = fmaxf(m0, m1);
    float w0 = __expf(m0 - m), w1 = __expf(m1 - m);
    float S = g_as[base + 0] * w0 + g_as[base + 1] * w1;
    const size_t ob = ((size_t)b * HH + h) * HD + j;
    float o = g_ao[ob] * w0 + g_ao[(size_t)BB * HH * HD + ob] * w1;
    xs[j * 12 + bb] = o / S;
    __syncthreads();
}

// ---------------- gemv core: 32 cols x 8 batches over DS K-dims ----------
template <int DS>
__device__ __forceinline__ void gemv_core(const float* __restrict__ W, int N,
                                          int d0, int c0,
                                          float* __restrict__ out, int ldo,
                                          int b0, float* xs, float* red) {
    const int tid = threadIdx.x, lane = tid & 31, w = tid >> 5;
    constexpr int DW = DS / 8;
    const float* Wp = W + (size_t)(d0 + w * DW) * N + c0 + lane;
    const float* xp = xs + (size_t)(w * DW) * 12;
    float a0 = 0, a1 = 0, a2 = 0, a3 = 0, a4 = 0, a5 = 0, a6 = 0, a7 = 0;
#pragma unroll
    for (int d = 0; d < DW; d++) {
        float wv = Wp[(size_t)d * N];
        float4 xa = *(const float4*)(xp + d * 12);
        float4 xb = *(const float4*)(xp + d * 12 + 4);
        a0 += xa.x * wv; a1 += xa.y * wv; a2 += xa.z * wv; a3 += xa.w * wv;
        a4 += xb.x * wv; a5 += xb.y * wv; a6 += xb.z * wv; a7 += xb.w * wv;
    }
    float* rp = red + (size_t)tid * 9;
    rp[0] = a0; rp[1] = a1; rp[2] = a2; rp[3] = a3;
    rp[4] = a4; rp[5] = a5; rp[6] = a6; rp[7] = a7;
    __syncthreads();
    const int cc = tid & 31, bb = tid >> 5;
    float v = 0.f;
#pragma unroll
    for (int w2 = 0; w2 < 8; w2++) v += red[(size_t)(w2 * 32 + cc) * 9 + bb];
    out[(size_t)(b0 + bb) * ldo + c0 + cc] = v;
    __syncthreads();
}

// ---------------- attention chunk: one (b, h, c) ----------------
__device__ void attn_chunk(const float* __restrict__ Kc, const float* __restrict__ Vc,
                           const float* __restrict__ bq,
                           const int* __restrict__ kvlen,
                           int b, int h, int c, float* sm) {
    float* sc   = sm;         // [392]
    float* qs   = sm + 392;   // [32]
    float* kns  = sm + 424;   // [32]
    float* vns  = sm + 456;   // [32]
    float* redv = sm + 488;   // [8][32]
    float* rr   = sm + 744;   // [8]
    float* fin  = sm + 752;   // [2]

    const int tid = threadIdx.x, wid = tid >> 5, lane = tid & 31;
    const int T = kvlen[b];
    const int Ttot = T + 1;
    const int CH = (Ttot + NCH - 1) / NCH;
    const int t0 = c * CH;
    const int t1 = (t0 + CH < Ttot) ? (t0 + CH) : Ttot;
    const float scale = 0.17677669529663687f;

    // merge qkv partials (4 slices) for q / k_new / v_new
    if (tid < 96) {
        int which = tid >> 5, j = tid & 31;
        int col = which * DD + h * HD + j;
        float v = bq[col];
#pragma unroll
        for (int s = 0; s < 4; s++) v += g_pqkv[(size_t)(s * BB + b) * NQKV + col];
        if (which == 0) qs[j] = v;
        else if (which == 1) kns[j] = v;
        else vns[j] = v;
    }
    __syncthreads();

    const int outi = (b * HH + h) * NCH + c;
    const size_t ob = ((size_t)b * HH + h) * HD;

    if (t1 <= t0) {
        if (tid == 0) { g_am[outi] = -1e30f; g_as[outi] = 0.f; }
        if (tid < HD) g_ao[(size_t)(c * BB) * HH * HD + ob + tid] = 0.f;
        return;
    }

    const float* Kb = Kc + ((size_t)b * HH + h) * TMAX * HD;
    const float* Vb = Vc + ((size_t)b * HH + h) * TMAX * HD;
    const int len = t1 - t0;

    // score pass: thread per timestep (row = one 128B line)
    for (int t = t0 + tid; t < t1; t += NT) {
        const float* kp = (t < T) ? (Kb + (size_t)t * HD) : kns;
        float s = 0.f;
#pragma unroll
        for (int i = 0; i < 8; i++) {
            float4 k4 = *(const float4*)(kp + i * 4);
            float4 q4 = *(const float4*)(qs + i * 4);
            s += k4.x * q4.x + k4.y * q4.y + k4.z * q4.z + k4.w * q4.w;
        }
        sc[t - t0] = s * scale;
    }
    __syncthreads();

    // chunk max
    float m = -1e30f;
    for (int i = tid; i < len; i += NT) m = fmaxf(m, sc[i]);
#pragma unroll
    for (int o = 16; o; o >>= 1) m = fmaxf(m, __shfl_xor_sync(0xffffffffu, m, o));
    if (lane == 0) rr[wid] = m;
    __syncthreads();
    if (tid == 0) {
        float mm = rr[0];
#pragma unroll
        for (int w = 1; w < 8; w++) mm = fmaxf(mm, rr[w]);
        fin[0] = mm;
    }
    __syncthreads();
    m = fin[0];

    // exp + sum
    float s = 0.f;
    for (int i = tid; i < len; i += NT) {
        float e = __expf(sc[i] - m);
        sc[i] = e;
        s += e;
    }
#pragma unroll
    for (int o = 16; o; o >>= 1) s += __shfl_xor_sync(0xffffffffu, s, o);
    if (lane == 0) rr[wid] = s;
    __syncthreads();
    if (tid == 0) {
        float ss = rr[0];
#pragma unroll
        for (int w = 1; w < 8; w++) ss += rr[w];
        g_am[outi] = m;
        g_as[outi] = ss;
    }

    // V pass: warp covers 4 timesteps/iter; 4 INDEPENDENT acc chains so 4
    // DRAM loads stay in flight (stride 128 outer loop).
    const int tq = lane >> 3, dq = lane & 7;
    float4 a0 = make_float4(0.f, 0.f, 0.f, 0.f);
    float4 a1 = a0, a2 = a0, a3 = a0;
    const int tb = t0 + wid * 4 + tq;
    for (int t = tb; t < t1; t += 128) {
        {
            float wgt = sc[t - t0];
            const float* vp = (t < T) ? (Vb + (size_t)t * HD) : vns;
            float4 v4 = *(const float4*)(vp + dq * 4);
            a0.x += wgt * v4.x; a0.y += wgt * v4.y;
            a0.z += wgt * v4.z; a0.w += wgt * v4.w;
        }
        if (t + 32 < t1) {
            float wgt = sc[t + 32 - t0];
            const float* vp = (t + 32 < T) ? (Vb + (size_t)(t + 32) * HD) : vns;
            float4 v4 = *(const float4*)(vp + dq * 4);
            a1.x += wgt * v4.x; a1.y += wgt * v4.y;
            a1.z += wgt * v4.z; a1.w += wgt * v4.w;
        }
        if (t + 64 < t1) {
            float wgt = sc[t + 64 - t0];
            const float* vp = (t + 64 < T) ? (Vb + (size_t)(t + 64) * HD) : vns;
            float4 v4 = *(const float4*)(vp + dq * 4);
            a2.x += wgt * v4.x; a2.y += wgt * v4.y;
            a2.z += wgt * v4.z; a2.w += wgt * v4.w;
        }
        if (t + 96 < t1) {
            float wgt = sc[t + 96 - t0];
            const float* vp = (t + 96 < T) ? (Vb + (size_t)(t + 96) * HD) : vns;
            float4 v4 = *(const float4*)(vp + dq * 4);
            a3.x += wgt * v4.x; a3.y += wgt * v4.y;
            a3.z += wgt * v4.z; a3.w += wgt * v4.w;
        }
    }
    float4 acc;
    acc.x = (a0.x + a1.x) + (a2.x + a3.x);
    acc.y = (a0.y + a1.y) + (a2.y + a3.y);
    acc.z = (a0.z + a1.z) + (a2.z + a3.z);
    acc.w = (a0.w + a1.w) + (a2.w + a3.w);
#pragma unroll
    for (int o = 8; o <= 16; o <<= 1) {
        acc.x += __shfl_xor_sync(0xffffffffu, acc.x, o);
        acc.y += __shfl_xor_sync(0xffffffffu, acc.y, o);
        acc.z += __shfl_xor_sync(0xffffffffu, acc.z, o);
        acc.w += __shfl_xor_sync(0xffffffffu, acc.w, o);
    }
    if (tq == 0) *(float4*)(redv + wid * 32 + dq * 4) = acc;
    __syncthreads();
    if (tid < HD) {
        float o = 0.f;
#pragma unroll
        for (int w = 0; w < 8; w++) o += redv[w * 32 + tid];
        g_ao[(size_t)(c * BB) * HH * HD + ob + tid] = o;
    }
}

// ---------------- LN stage: one batch, merge S partials + resid + bias ---
template <int S>
__device__ void ln_stage(const float* __restrict__ part,
                         const float* __restrict__ resid,
                         const float* __restrict__ bias,
                         const float* __restrict__ gam,
                         const float* __restrict__ bet,
                         float* __restrict__ out, int b, float* sm) {
    const int tid = threadIdx.x, lane = tid & 31, wid = tid >> 5;
    float v0, v1;
    {
        int j = tid;
        float t = resid[(size_t)b * DD + j] + bias[j];
#pragma unroll
        for (int s = 0; s < S; s++) t += part[(size_t)(s * BB + b) * DD + j];
        v0 = t;
        j = tid + 256;
        t = resid[(size_t)b * DD + j] + bias[j];
#pragma unroll
        for (int s = 0; s < S; s++) t += part[(size_t)(s * BB + b) * DD + j];
        v1 = t;
    }
    float s1 = v0 + v1, s2 = v0 * v0 + v1 * v1;
#pragma unroll
    for (int o = 16; o; o >>= 1) {
        s1 += __shfl_xor_sync(0xffffffffu, s1, o);
        s2 += __shfl_xor_sync(0xffffffffu, s2, o);
    }
    float* rs = sm; float* rq = sm + 8; float* mv = sm + 16;
    if (lane == 0) { rs[wid] = s1; rq[wid] = s2; }
    __syncthreads();
    if (tid == 0) {
        float a = 0.f, q = 0.f;
#pragma unroll
        for (int w = 0; w < 8; w++) { a += rs[w]; q += rq[w]; }
        float mean = a / DD;
        mv[0] = mean;
        mv[1] = rsqrtf(q / DD - mean * mean + 1e-5f);
    }
    __syncthreads();
    const float mean = mv[0], rstd = mv[1];
    out[(size_t)b * DD + tid] = (v0 - mean) * rstd * gam[tid] + bet[tid];
    out[(size_t)b * DD + tid + 256] =
        (v1 - mean) * rstd * gam[tid + 256] + bet[tid + 256];
    __syncthreads();
}

// ---------------- persistent kernel ----------------
__global__ void __launch_bounds__(NT, 4)
decoder_kernel(const float* __restrict__ x,
               const float* __restrict__ kc, const float* __restrict__ vc,
               const float* __restrict__ ln1g, const float* __restrict__ ln1b,
               const float* __restrict__ qkvw, const float* __restrict__ qkvb,
               const float* __restrict__ outw, const float* __restrict__ outb,
               const float* __restrict__ ln2g, const float* __restrict__ ln2b,
               const float* __restrict__ w1, const float* __restrict__ b1,
               const float* __restrict__ w2, const float* __restrict__ b2,
               const int* __restrict__ kvlen, float* __restrict__ dout) {
    extern __shared__ float sm[];
    float* xs  = sm;             // [128][12] max
    float* red = sm + 128 * 12;  // [256][9]

    for (int l = 0; l < LL; l++) {
        const float* Wq = qkvw + (size_t)l * DD * NQKV;
        const float* bq = qkvb + (size_t)l * NQKV;
        const float* Wo = outw + (size_t)l * DD * DD;
        const float* bo = outb + (size_t)l * DD;
        const float* W1 = w1 + (size_t)l * DD * DFF;
        const float* B1 = b1 + (size_t)l * DFF;
        const float* W2 = w2 + (size_t)l * DFF * DD;
        const float* Kc = kc + (size_t)l * BB * HH * TMAX * HD;
        const float* Vc = vc + (size_t)l * BB * HH * TMAX * HD;

        // S0: produce g_h (x for l==0, else LN2 of prev layer). 16 vblocks.
        if (l == 0) {
            for (int i = blockIdx.x * NT + threadIdx.x; i < BB * DD;
                 i += gridDim.x * NT)
                g_h[i] = x[i];
        } else {
            for (int vb = blockIdx.x; vb < 16; vb += gridDim.x)
                ln_stage<16>(g_p2, g_h1, b2 + (size_t)(l - 1) * DD,
                             ln2g + (size_t)(l - 1) * DD,
                             ln2b + (size_t)(l - 1) * DD, g_h, vb, sm);
        }
        gsync();

        // S1: qkv split-K4 (DS=128). 384 vblocks (1 round on 608).
        for (int vb = blockIdx.x; vb < 384; vb += gridDim.x) {
            int ks = vb & 3, b0 = ((vb >> 2) & 1) * 8, c0 = (vb >> 3) * 32;
            preload_plain<128>(g_h, DD, ks * 128, b0, xs);
            gemv_core<128>(Wq, NQKV, ks * 128, c0,
                           g_pqkv + (size_t)ks * BB * NQKV, NQKV, b0, xs, red);
        }
        gsync();

        // S2: attention T-split 2. 512 vblocks (1 round).
        for (int vb = blockIdx.x; vb < 512; vb += gridDim.x) {
            int c = vb & 1, h = (vb >> 1) & 15, b = vb >> 5;
            attn_chunk(Kc, Vc, bq, kvlen, b, h, c, sm);
        }
        gsync();

        // S3: outproj split-K16 (DS=32), attn merge in preload. 512 vblocks.
        for (int vb = blockIdx.x; vb < 512; vb += gridDim.x) {
            int ks = vb & 15, b0 = ((vb >> 4) & 1) * 8, c0 = (vb >> 5) * 32;
            preload_attn(ks, b0, xs);  // h == ks since DS == HD
            gemv_core<32>(Wo, DD, ks * 32, c0,
                          g_po + (size_t)ks * BB * DD, DD, b0, xs, red);
        }
        gsync();

        // S4: LN1 (merge 16 outproj partials + residual g_h + bo). 16 vblocks.
        for (int vb = blockIdx.x; vb < 16; vb += gridDim.x)
            ln_stage<16>(g_po, g_h, bo, ln1g + (size_t)l * DD,
                         ln1b + (size_t)l * DD, g_h1, vb, sm);
        gsync();

        // S5: mlp1 split-K4 (DS=128). 512 vblocks.
        for (int vb = blockIdx.x; vb < 512; vb += gridDim.x) {
            int ks = vb & 3, b0 = ((vb >> 2) & 1) * 8, c0 = (vb >> 3) * 32;
            preload_plain<128>(g_h1, DD, ks * 128, b0, xs);
            gemv_core<128>(W1, DFF, ks * 128, c0,
                           g_pm1 + (size_t)ks * BB * DFF, DFF, b0, xs, red);
        }
        gsync();

        // S6: mlp2 split-K16 (DS=128), relu+merge in preload. 512 vblocks.
        for (int vb = blockIdx.x; vb < 512; vb += gridDim.x) {
            int ks = vb & 15, b0 = ((vb >> 4) & 1) * 8, c0 = (vb >> 5) * 32;
            preload_relu(B1, ks * 128, b0, xs);
            gemv_core<128>(W2, DD, ks * 128, c0,
                           g_p2 + (size_t)ks * BB * DD, DD, b0, xs, red);
        }
        gsync();
    }

    // final: LN2 of last layer -> d_out. 16 vblocks.
    for (int vb = blockIdx.x; vb < 16; vb += gridDim.x)
        ln_stage<16>(g_p2, g_h1, b2 + (size_t)(LL - 1) * DD,
                     ln2g + (size_t)(LL - 1) * DD,
                     ln2b + (size_t)(LL - 1) * DD, dout, vb, sm);
}

// ---------------- launcher ----------------
extern "C" void kernel_launch(void* const* d_in, const int* in_sizes, int n_in,
                              void* d_out, int out_size) {
    (void)in_sizes; (void)n_in; (void)out_size;
    const float* x    = (const float*)d_in[0];
    const float* kc   = (const float*)d_in[1];
    const float* vc   = (const float*)d_in[2];
    const float* ln1g = (const float*)d_in[3];
    const float* ln1b = (const float*)d_in[4];
    const float* qkvw = (const float*)d_in[5];
    const float* qkvb = (const float*)d_in[6];
    const float* outw = (const float*)d_in[7];
    const float* outb = (const float*)d_in[8];
    const float* ln2g = (const float*)d_in[9];
    const float* ln2b = (const float*)d_in[10];
    const float* w1   = (const float*)d_in[11];
    const float* b1   = (const float*)d_in[12];
    const float* w2   = (const float*)d_in[13];
    const float* b2   = (const float*)d_in[14];
    const int* kvlen  = (const int*)d_in[16];

    static int grid = 0;
    const int SMEM = (128 * 12 + 256 * 9) * 4;  // 15360 bytes
    if (!grid) {
        cudaFuncSetAttribute(decoder_kernel,
                             cudaFuncAttributeMaxDynamicSharedMemorySize, SMEM);
        int dev = 0;
        cudaGetDevice(&dev);
        cudaDeviceProp prop;
        cudaGetDeviceProperties(&prop, dev);
        int occ = 0;
        cudaOccupancyMaxActiveBlocksPerMultiprocessor(&occ, decoder_kernel,
                                                      NT, SMEM);
        if (occ < 1) occ = 1;
        if (occ > 4) occ = 4;
        grid = prop.multiProcessorCount * occ;
    }

    decoder_kernel<<<grid, NT, SMEM>>>(
        x, kc, vc, ln1g, ln1b, qkvw, qkvb, outw, outb, ln2g, ln2b,
        w1, b1, w2, b2, kvlen, (float*)d_out);
}